// round 4
// baseline (speedup 1.0000x reference)
#include <cuda_runtime.h>
#include <cuda_fp16.h>
#include <cstdint>

#define N_NODES 100000
#define N_EDGES 1000000
#define D 64
#define NEG_SLOPE 0.01f

// ---------------- scratch (no allocations allowed) ----------------
__device__ int   g_degOi[N_NODES];
__device__ int   g_degIi[N_NODES];
__device__ float g_oisq [N_NODES];
__device__ float g_iisq [N_NODES];
__device__ int2  g_rows [N_NODES];        // {row start, in-degree}
__device__ int   g_cursor[N_NODES];       // fill cursors
__device__ int   g_total;                 // global row-offset cursor
__device__ int   g_esrc[N_EDGES];         // CSR column (src) array
__device__ __align__(16) half2 g_xh [(size_t)N_NODES * 32];  // x * oisq, fp16
__device__ __align__(16) half2 g_h1h[(size_t)N_NODES * 32];  // h1 * oisq, fp16

// ---------------- degree histogram (4 edges/thread) ----------------
// counters are zero on entry: BSS-zero on first call, re-zeroed by k_alloc after.
__global__ void k_deg(const int* __restrict__ src, const int* __restrict__ dst) {
    int t = blockIdx.x * blockDim.x + threadIdx.x;
    int e0 = t * 4;
    if (e0 + 4 <= N_EDGES) {
        int4 s = *(const int4*)(src + e0);
        int4 d = *(const int4*)(dst + e0);
        atomicAdd(&g_degOi[s.x], 1); atomicAdd(&g_degOi[s.y], 1);
        atomicAdd(&g_degOi[s.z], 1); atomicAdd(&g_degOi[s.w], 1);
        atomicAdd(&g_degIi[d.x], 1); atomicAdd(&g_degIi[d.y], 1);
        atomicAdd(&g_degIi[d.z], 1); atomicAdd(&g_degIi[d.w], 1);
    } else {
        for (int e = e0; e < N_EDGES; e++) {
            atomicAdd(&g_degOi[src[e]], 1);
            atomicAdd(&g_degIi[dst[e]], 1);
        }
    }
}

// ---------------- row allocation + norms; zero counters for next replay ------
__global__ void k_alloc() {
    int i = blockIdx.x * blockDim.x + threadIdx.x;
    if (i >= N_NODES) return;
    int di = g_degIi[i];
    int dO = g_degOi[i];
    int row = atomicAdd(&g_total, di);     // grouping only; order irrelevant
    g_rows[i] = make_int2(row, di);
    g_cursor[i] = row;
    g_oisq[i] = rsqrtf((float)max(dO, 1));
    g_iisq[i] = rsqrtf((float)max(di, 1));
    g_degOi[i] = 0;                        // reset for next graph replay
    g_degIi[i] = 0;
}

// ---------------- CSR fill (4 edges/thread) ----------------
__global__ void k_fill(const int* __restrict__ src, const int* __restrict__ dst) {
    int t = blockIdx.x * blockDim.x + threadIdx.x;
    int e0 = t * 4;
    if (e0 + 4 <= N_EDGES) {
        int4 s = *(const int4*)(src + e0);
        int4 d = *(const int4*)(dst + e0);
        g_esrc[atomicAdd(&g_cursor[d.x], 1)] = s.x;
        g_esrc[atomicAdd(&g_cursor[d.y], 1)] = s.y;
        g_esrc[atomicAdd(&g_cursor[d.z], 1)] = s.z;
        g_esrc[atomicAdd(&g_cursor[d.w], 1)] = s.w;
    } else {
        for (int e = e0; e < N_EDGES; e++)
            g_esrc[atomicAdd(&g_cursor[dst[e]], 1)] = src[e];
    }
}

// ---------------- convert x -> fp16 pre-scaled by oisq; reset g_total --------
__global__ void k_convert(const float* __restrict__ x) {
    int t = blockIdx.x * blockDim.x + threadIdx.x;
    if (t == 0) g_total = 0;
    if (t >= N_NODES * (D / 4)) return;
    int node = t >> 4;                     // 16 float4 per row
    float sc = g_oisq[node];
    float4 v = __ldg((const float4*)x + t);
    half2 h0 = __floats2half2_rn(v.x * sc, v.y * sc);
    half2 h1 = __floats2half2_rn(v.z * sc, v.w * sc);
    g_xh[t * 2 + 0] = h0;
    g_xh[t * 2 + 1] = h1;
}

// =====================================================================
// Fused layers: warp-per-node CSR aggregate (fp16, 1 line/edge) -> GEMM
// Block: 256 threads = 8 warps; 64 nodes/block; warp serves 8 nodes.
// =====================================================================

// aggregate one node's in-edges into float2 acc (lane covers feats 2l, 2l+1)
__device__ __forceinline__ float2 warp_aggregate(const half2* __restrict__ feat,
                                                 int node, int lane) {
    float2 acc = make_float2(0.f, 0.f);
    int2 rd = g_rows[node];
    int start = rd.x, deg = rd.y;
    int i = 0;
    int p0 = 0, p1 = 0, p2 = 0, p3 = 0;
    if (i + 4 <= deg) {
        p0 = __ldg(&g_esrc[start + 0]); p1 = __ldg(&g_esrc[start + 1]);
        p2 = __ldg(&g_esrc[start + 2]); p3 = __ldg(&g_esrc[start + 3]);
    }
    while (i + 4 <= deg) {
        int s0 = p0, s1 = p1, s2 = p2, s3 = p3;
        int ni = i + 4;
        if (ni + 4 <= deg) {               // prefetch next index group
            p0 = __ldg(&g_esrc[start + ni + 0]);
            p1 = __ldg(&g_esrc[start + ni + 1]);
            p2 = __ldg(&g_esrc[start + ni + 2]);
            p3 = __ldg(&g_esrc[start + ni + 3]);
        }
        half2 v0 = __ldg(feat + s0 * 32 + lane);
        half2 v1 = __ldg(feat + s1 * 32 + lane);
        half2 v2 = __ldg(feat + s2 * 32 + lane);
        half2 v3 = __ldg(feat + s3 * 32 + lane);
        float2 f0 = __half22float2(v0), f1 = __half22float2(v1);
        float2 f2 = __half22float2(v2), f3 = __half22float2(v3);
        acc.x += (f0.x + f1.x) + (f2.x + f3.x);
        acc.y += (f0.y + f1.y) + (f2.y + f3.y);
        i = ni;
    }
    for (; i < deg; i++) {
        int s = __ldg(&g_esrc[start + i]);
        float2 f = __half22float2(__ldg(feat + s * 32 + lane));
        acc.x += f.x; acc.y += f.y;
    }
    return acc;
}

// Layer 1: agg = sum xh[src]; v = agg*iisq; h1h = half(lrelu(v@W1+b1)*oisq)
__global__ void __launch_bounds__(256) k_layer1(
    const float* __restrict__ W, const float* __restrict__ b)
{
    __shared__ float sW[D * D];
    __shared__ float sV[64][D + 4];
    int tid = threadIdx.x;
    int base = blockIdx.x * 64;
    int warp = tid >> 5, lane = tid & 31;

    for (int i = tid; i < D * D; i += 256) sW[i] = W[i];

#pragma unroll 1
    for (int nn = 0; nn < 8; nn++) {
        int nw = warp * 8 + nn;
        int node = base + nw;
        float2 acc = make_float2(0.f, 0.f);
        if (node < N_NODES) {
            acc = warp_aggregate(g_xh, node, lane);
            float fi = g_iisq[node];
            acc.x *= fi; acc.y *= fi;
        }
        sV[nw][lane * 2 + 0] = acc.x;
        sV[nw][lane * 2 + 1] = acc.y;
    }
    __syncthreads();

    // GEMM 64x64 @ 64x64, 4x4 register tile
    int nq = tid >> 4, oq = tid & 15;
    float acc[4][4];
#pragma unroll
    for (int i = 0; i < 4; i++)
#pragma unroll
        for (int j = 0; j < 4; j++) acc[i][j] = 0.f;
#pragma unroll
    for (int k = 0; k < D; k++) {
        float4 w = *(const float4*)&sW[k * D + oq * 4];
#pragma unroll
        for (int i = 0; i < 4; i++) {
            float v = sV[nq * 4 + i][k];
            acc[i][0] += v * w.x; acc[i][1] += v * w.y;
            acc[i][2] += v * w.z; acc[i][3] += v * w.w;
        }
    }
    float b4[4] = {b[oq*4+0], b[oq*4+1], b[oq*4+2], b[oq*4+3]};
#pragma unroll
    for (int i = 0; i < 4; i++) {
        int on = base + nq * 4 + i;
        if (on >= N_NODES) continue;
        float sc = __ldg(&g_oisq[on]);         // pre-scale for layer-2 gather
        float y0 = acc[i][0]+b4[0]; y0 = (y0>0.f)?y0:NEG_SLOPE*y0;
        float y1 = acc[i][1]+b4[1]; y1 = (y1>0.f)?y1:NEG_SLOPE*y1;
        float y2 = acc[i][2]+b4[2]; y2 = (y2>0.f)?y2:NEG_SLOPE*y2;
        float y3 = acc[i][3]+b4[3]; y3 = (y3>0.f)?y3:NEG_SLOPE*y3;
        half2 h0 = __floats2half2_rn(y0 * sc, y1 * sc);
        half2 h1 = __floats2half2_rn(y2 * sc, y3 * sc);
        g_h1h[(size_t)on * 32 + oq * 2 + 0] = h0;
        g_h1h[(size_t)on * 32 + oq * 2 + 1] = h1;
    }
}

// Layer 2 + classifier
__global__ void __launch_bounds__(256) k_layer2(
    const float* __restrict__ W2, const float* __restrict__ b2,
    const float* __restrict__ Wc, const float* __restrict__ bc,
    float* __restrict__ out)
{
    __shared__ float sW[D * D];
    __shared__ float sV[64][D + 4];
    __shared__ float sWc[D * 2];
    int tid = threadIdx.x;
    int base = blockIdx.x * 64;
    int warp = tid >> 5, lane = tid & 31;

    for (int i = tid; i < D * D; i += 256) sW[i] = W2[i];
    if (tid < D * 2) sWc[tid] = Wc[tid];

#pragma unroll 1
    for (int nn = 0; nn < 8; nn++) {
        int nw = warp * 8 + nn;
        int node = base + nw;
        float2 acc = make_float2(0.f, 0.f);
        if (node < N_NODES) {
            acc = warp_aggregate(g_h1h, node, lane);
            float fi = g_iisq[node];
            acc.x *= fi; acc.y *= fi;
        }
        sV[nw][lane * 2 + 0] = acc.x;
        sV[nw][lane * 2 + 1] = acc.y;
    }
    __syncthreads();

    int nq = tid >> 4, oq = tid & 15;
    float acc[4][4];
#pragma unroll
    for (int i = 0; i < 4; i++)
#pragma unroll
        for (int j = 0; j < 4; j++) acc[i][j] = 0.f;
#pragma unroll
    for (int k = 0; k < D; k++) {
        float4 w = *(const float4*)&sW[k * D + oq * 4];
#pragma unroll
        for (int i = 0; i < 4; i++) {
            float v = sV[nq * 4 + i][k];
            acc[i][0] += v * w.x; acc[i][1] += v * w.y;
            acc[i][2] += v * w.z; acc[i][3] += v * w.w;
        }
    }
    __syncthreads();   // all sV reads done before overwrite

    float b4[4] = {b2[oq*4+0], b2[oq*4+1], b2[oq*4+2], b2[oq*4+3]};
#pragma unroll
    for (int i = 0; i < 4; i++) {
#pragma unroll
        for (int j = 0; j < 4; j++) {
            float y = acc[i][j] + b4[j];
            y = (y > 0.f) ? y : NEG_SLOPE * y;
            sV[nq * 4 + i][oq * 4 + j] = y;
        }
    }
    __syncthreads();

    if (tid < 128) {
        int n = tid >> 1, c = tid & 1;
        int on = base + n;
        if (on < N_NODES) {
            float s = bc[c];
#pragma unroll
            for (int k = 0; k < D; k++) s += sV[n][k] * sWc[k * 2 + c];
            out[(size_t)on * 2 + c] = s;
        }
    }
}

// ---------------- launch ----------------
extern "C" void kernel_launch(void* const* d_in, const int* in_sizes, int n_in,
                              void* d_out, int out_size) {
    const float* x   = (const float*)d_in[0];
    const int*   src = (const int*)  d_in[1];
    const int*   dst = (const int*)  d_in[2];
    const float* W1  = (const float*)d_in[3];
    const float* b1  = (const float*)d_in[4];
    const float* W2  = (const float*)d_in[5];
    const float* b2  = (const float*)d_in[6];
    const float* Wc  = (const float*)d_in[7];
    const float* bc  = (const float*)d_in[8];
    float* out = (float*)d_out;

    const int edgeThreads = (N_EDGES + 3) / 4;
    k_deg    <<<(edgeThreads + 255) / 256, 256>>>(src, dst);
    k_alloc  <<<(N_NODES + 255) / 256, 256>>>();
    k_convert<<<(N_NODES * (D / 4) + 255) / 256, 256>>>(x);
    k_fill   <<<(edgeThreads + 255) / 256, 256>>>(src, dst);

    k_layer1<<<(N_NODES + 63) / 64, 256>>>(W1, b1);
    k_layer2<<<(N_NODES + 63) / 64, 256>>>(W2, b2, Wc, bc, out);
}

// round 5
// speedup vs baseline: 1.2363x; 1.2363x over previous
#include <cuda_runtime.h>
#include <cuda_fp16.h>
#include <cstdint>

#define N_NODES 100000
#define N_EDGES 1000000
#define D 64
#define NEG_SLOPE 0.01f

// ---------------- scratch (no allocations allowed) ----------------
__device__ int   g_degOi[N_NODES];
__device__ int   g_degIi[N_NODES];
__device__ float g_oisq [N_NODES];
__device__ float g_iisq [N_NODES];
__device__ int2  g_rows [N_NODES];        // {row start, in-degree}
__device__ int   g_cursor[N_NODES];       // fill cursors
__device__ int   g_total;                 // global row-offset cursor
__device__ int   g_esrc[N_EDGES];         // CSR column (src) array
__device__ __align__(16) half2 g_xh [(size_t)N_NODES * 32];  // x * oisq, fp16 (128B rows)
__device__ __align__(16) half2 g_h1h[(size_t)N_NODES * 32];  // h1 * oisq, fp16

// ---------------- degree histogram (4 edges/thread; REDG, no return) --------
// counters are zero on entry: BSS-zero on first call, re-zeroed by k_alloc.
__global__ void k_deg(const int* __restrict__ src, const int* __restrict__ dst) {
    int t = blockIdx.x * blockDim.x + threadIdx.x;
    int e0 = t * 4;
    if (e0 + 4 <= N_EDGES) {
        int4 s = *(const int4*)(src + e0);
        int4 d = *(const int4*)(dst + e0);
        atomicAdd(&g_degOi[s.x], 1); atomicAdd(&g_degOi[s.y], 1);
        atomicAdd(&g_degOi[s.z], 1); atomicAdd(&g_degOi[s.w], 1);
        atomicAdd(&g_degIi[d.x], 1); atomicAdd(&g_degIi[d.y], 1);
        atomicAdd(&g_degIi[d.z], 1); atomicAdd(&g_degIi[d.w], 1);
    } else {
        for (int e = e0; e < N_EDGES; e++) {
            atomicAdd(&g_degOi[src[e]], 1);
            atomicAdd(&g_degIi[dst[e]], 1);
        }
    }
}

// ---------------- row allocation + norms; zero counters for next replay ------
__global__ void k_alloc() {
    int i = blockIdx.x * blockDim.x + threadIdx.x;
    if (i >= N_NODES) return;
    int di = g_degIi[i];
    int dO = g_degOi[i];
    int row = atomicAdd(&g_total, di);     // grouping only; order irrelevant
    g_rows[i] = make_int2(row, di);
    g_cursor[i] = row;
    g_oisq[i] = rsqrtf((float)max(dO, 1));
    g_iisq[i] = rsqrtf((float)max(di, 1));
    g_degOi[i] = 0;                        // reset for next replay
    g_degIi[i] = 0;
}

// ---------------- convert x -> fp16 pre-scaled by oisq; reset g_total --------
__global__ void k_convert(const float* __restrict__ x) {
    int t = blockIdx.x * blockDim.x + threadIdx.x;
    if (t == 0) g_total = 0;
    if (t >= N_NODES * (D / 4)) return;
    int node = t >> 4;                     // 16 float4 per row
    float sc = g_oisq[node];
    float4 v = __ldg((const float4*)x + t);
    g_xh[t * 2 + 0] = __floats2half2_rn(v.x * sc, v.y * sc);
    g_xh[t * 2 + 1] = __floats2half2_rn(v.z * sc, v.w * sc);
}

// ---------------- CSR fill (4 edges/thread, atomics batched) ----------------
__global__ void k_fill(const int* __restrict__ src, const int* __restrict__ dst) {
    int t = blockIdx.x * blockDim.x + threadIdx.x;
    int e0 = t * 4;
    if (e0 + 4 <= N_EDGES) {
        int4 s = *(const int4*)(src + e0);
        int4 d = *(const int4*)(dst + e0);
        int p0 = atomicAdd(&g_cursor[d.x], 1);
        int p1 = atomicAdd(&g_cursor[d.y], 1);
        int p2 = atomicAdd(&g_cursor[d.z], 1);
        int p3 = atomicAdd(&g_cursor[d.w], 1);
        g_esrc[p0] = s.x; g_esrc[p1] = s.y;
        g_esrc[p2] = s.z; g_esrc[p3] = s.w;
    } else {
        for (int e = e0; e < N_EDGES; e++)
            g_esrc[atomicAdd(&g_cursor[dst[e]], 1)] = src[e];
    }
}

// =====================================================================
// Fused layers: fp16 gather, 4 lanes/node, 8 nodes concurrently/warp,
// edge loop unrolled x2 with index prefetch (4 uint4 in flight/lane).
// Block: 256 threads, 64 nodes.
// =====================================================================

// accumulate 8 halves (one uint4) into 4 float2 accumulators
#define ACC_U4(V, A)                                                \
    do {                                                            \
        const half2* hv = (const half2*)&(V);                       \
        float2 f0 = __half22float2(hv[0]);                          \
        float2 f1 = __half22float2(hv[1]);                          \
        float2 f2 = __half22float2(hv[2]);                          \
        float2 f3 = __half22float2(hv[3]);                          \
        (A)[0].x += f0.x; (A)[0].y += f0.y;                         \
        (A)[1].x += f1.x; (A)[1].y += f1.y;                         \
        (A)[2].x += f2.x; (A)[2].y += f2.y;                         \
        (A)[3].x += f3.x; (A)[3].y += f3.y;                         \
    } while (0)

// lane l of a 4-lane group covers feats [8l,8l+8) and [32+8l,32+8l+8)
__device__ __forceinline__ void group_aggregate(const uint4* __restrict__ feat,
                                                int node, int l,
                                                float2 accA[4], float2 accB[4]) {
    int2 rd = g_rows[node];
    int start = rd.x, deg = rd.y;
    int i = 0;
    int s0 = 0, s1 = 0;
    if (deg >= 2) { s0 = __ldg(&g_esrc[start]); s1 = __ldg(&g_esrc[start + 1]); }
    for (; i + 2 <= deg; ) {
        int t0 = s0, t1 = s1;
        i += 2;
        if (i + 2 <= deg) {                    // prefetch next pair of indices
            s0 = __ldg(&g_esrc[start + i]);
            s1 = __ldg(&g_esrc[start + i + 1]);
        }
        uint4 va0 = __ldg(feat + (size_t)t0 * 8 + l);
        uint4 vb0 = __ldg(feat + (size_t)t0 * 8 + 4 + l);
        uint4 va1 = __ldg(feat + (size_t)t1 * 8 + l);
        uint4 vb1 = __ldg(feat + (size_t)t1 * 8 + 4 + l);
        ACC_U4(va0, accA); ACC_U4(vb0, accB);
        ACC_U4(va1, accA); ACC_U4(vb1, accB);
    }
    if (i < deg) {
        int t0 = __ldg(&g_esrc[start + i]);
        uint4 va0 = __ldg(feat + (size_t)t0 * 8 + l);
        uint4 vb0 = __ldg(feat + (size_t)t0 * 8 + 4 + l);
        ACC_U4(va0, accA); ACC_U4(vb0, accB);
    }
}

// phase A shared by both layers: aggregate block's 64 nodes into sV
__device__ __forceinline__ void aggregate_phase(const uint4* __restrict__ feat,
                                                int base, int tid,
                                                float sV[64][D + 4]) {
    int g = tid >> 2, l = tid & 3;
    int gn = base + g;
    float2 accA[4] = {{0,0},{0,0},{0,0},{0,0}};
    float2 accB[4] = {{0,0},{0,0},{0,0},{0,0}};
    if (gn < N_NODES) {
        group_aggregate(feat, gn, l, accA, accB);
        float fi = g_iisq[gn];
#pragma unroll
        for (int j = 0; j < 4; j++) {
            accA[j].x *= fi; accA[j].y *= fi;
            accB[j].x *= fi; accB[j].y *= fi;
        }
    }
#pragma unroll
    for (int j = 0; j < 4; j++) {
        sV[g][8 * l + 2 * j + 0]      = accA[j].x;
        sV[g][8 * l + 2 * j + 1]      = accA[j].y;
        sV[g][32 + 8 * l + 2 * j + 0] = accB[j].x;
        sV[g][32 + 8 * l + 2 * j + 1] = accB[j].y;
    }
}

// Layer 1: agg = sum xh[src]; v = agg*iisq; h1h = half(lrelu(v@W1+b1)*oisq)
__global__ void __launch_bounds__(256) k_layer1(
    const float* __restrict__ W, const float* __restrict__ b)
{
    __shared__ float sW[D * D];
    __shared__ float sV[64][D + 4];
    int tid = threadIdx.x;
    int base = blockIdx.x * 64;

    for (int i = tid; i < D * D; i += 256) sW[i] = W[i];

    aggregate_phase((const uint4*)g_xh, base, tid, sV);
    __syncthreads();

    // GEMM 64x64 @ 64x64, 4x4 register tile
    int nq = tid >> 4, oq = tid & 15;
    float acc[4][4];
#pragma unroll
    for (int i = 0; i < 4; i++)
#pragma unroll
        for (int j = 0; j < 4; j++) acc[i][j] = 0.f;
#pragma unroll
    for (int k = 0; k < D; k++) {
        float4 w = *(const float4*)&sW[k * D + oq * 4];
#pragma unroll
        for (int i = 0; i < 4; i++) {
            float v = sV[nq * 4 + i][k];
            acc[i][0] += v * w.x; acc[i][1] += v * w.y;
            acc[i][2] += v * w.z; acc[i][3] += v * w.w;
        }
    }
    float b4[4] = {b[oq*4+0], b[oq*4+1], b[oq*4+2], b[oq*4+3]};
#pragma unroll
    for (int i = 0; i < 4; i++) {
        int on = base + nq * 4 + i;
        if (on >= N_NODES) continue;
        float sc = __ldg(&g_oisq[on]);         // pre-scale for layer-2 gather
        float y0 = acc[i][0]+b4[0]; y0 = (y0>0.f)?y0:NEG_SLOPE*y0;
        float y1 = acc[i][1]+b4[1]; y1 = (y1>0.f)?y1:NEG_SLOPE*y1;
        float y2 = acc[i][2]+b4[2]; y2 = (y2>0.f)?y2:NEG_SLOPE*y2;
        float y3 = acc[i][3]+b4[3]; y3 = (y3>0.f)?y3:NEG_SLOPE*y3;
        g_h1h[(size_t)on * 32 + oq * 2 + 0] = __floats2half2_rn(y0 * sc, y1 * sc);
        g_h1h[(size_t)on * 32 + oq * 2 + 1] = __floats2half2_rn(y2 * sc, y3 * sc);
    }
}

// Layer 2 + classifier
__global__ void __launch_bounds__(256) k_layer2(
    const float* __restrict__ W2, const float* __restrict__ b2,
    const float* __restrict__ Wc, const float* __restrict__ bc,
    float* __restrict__ out)
{
    __shared__ float sW[D * D];
    __shared__ float sV[64][D + 4];
    __shared__ float sWc[D * 2];
    int tid = threadIdx.x;
    int base = blockIdx.x * 64;

    for (int i = tid; i < D * D; i += 256) sW[i] = W2[i];
    if (tid < D * 2) sWc[tid] = Wc[tid];

    aggregate_phase((const uint4*)g_h1h, base, tid, sV);
    __syncthreads();

    int nq = tid >> 4, oq = tid & 15;
    float acc[4][4];
#pragma unroll
    for (int i = 0; i < 4; i++)
#pragma unroll
        for (int j = 0; j < 4; j++) acc[i][j] = 0.f;
#pragma unroll
    for (int k = 0; k < D; k++) {
        float4 w = *(const float4*)&sW[k * D + oq * 4];
#pragma unroll
        for (int i = 0; i < 4; i++) {
            float v = sV[nq * 4 + i][k];
            acc[i][0] += v * w.x; acc[i][1] += v * w.y;
            acc[i][2] += v * w.z; acc[i][3] += v * w.w;
        }
    }
    __syncthreads();   // all sV reads done before overwrite

    float b4[4] = {b2[oq*4+0], b2[oq*4+1], b2[oq*4+2], b2[oq*4+3]};
#pragma unroll
    for (int i = 0; i < 4; i++) {
#pragma unroll
        for (int j = 0; j < 4; j++) {
            float y = acc[i][j] + b4[j];
            y = (y > 0.f) ? y : NEG_SLOPE * y;
            sV[nq * 4 + i][oq * 4 + j] = y;
        }
    }
    __syncthreads();

    if (tid < 128) {
        int n = tid >> 1, c = tid & 1;
        int on = base + n;
        if (on < N_NODES) {
            float s = bc[c];
#pragma unroll
            for (int k = 0; k < D; k++) s += sV[n][k] * sWc[k * 2 + c];
            out[(size_t)on * 2 + c] = s;
        }
    }
}

// ---------------- launch ----------------
extern "C" void kernel_launch(void* const* d_in, const int* in_sizes, int n_in,
                              void* d_out, int out_size) {
    const float* x   = (const float*)d_in[0];
    const int*   src = (const int*)  d_in[1];
    const int*   dst = (const int*)  d_in[2];
    const float* W1  = (const float*)d_in[3];
    const float* b1  = (const float*)d_in[4];
    const float* W2  = (const float*)d_in[5];
    const float* b2  = (const float*)d_in[6];
    const float* Wc  = (const float*)d_in[7];
    const float* bc  = (const float*)d_in[8];
    float* out = (float*)d_out;

    const int edgeThreads = (N_EDGES + 3) / 4;
    k_deg    <<<(edgeThreads + 255) / 256, 256>>>(src, dst);
    k_alloc  <<<(N_NODES + 255) / 256, 256>>>();
    k_convert<<<(N_NODES * (D / 4) + 255) / 256, 256>>>(x);
    k_fill   <<<(edgeThreads + 255) / 256, 256>>>(src, dst);

    k_layer1<<<(N_NODES + 63) / 64, 256>>>(W1, b1);
    k_layer2<<<(N_NODES + 63) / 64, 256>>>(W2, b2, Wc, bc, out);
}

// round 6
// speedup vs baseline: 1.3733x; 1.1108x over previous
#include <cuda_runtime.h>
#include <cuda_fp16.h>
#include <mma.h>
#include <cstdint>

using namespace nvcuda;

#define N_NODES 100000
#define N_EDGES 1000000
#define D 64
#define NEG_SLOPE 0.01f

#define LDA 72   // half leading dim for A/B tiles (144B, 16B-multiple)
#define LDC 68   // float leading dim for C tile (272B, 16B-multiple)

// ---------------- scratch (no allocations allowed) ----------------
__device__ int   g_degOi[N_NODES];
__device__ int   g_degIi[N_NODES];
__device__ float g_oisq [N_NODES];
__device__ float g_iisq [N_NODES];
__device__ int2  g_rows [N_NODES];        // {row start, in-degree}
__device__ int   g_cursor[N_NODES];       // fill cursors
__device__ int   g_total;                 // global row-offset cursor
__device__ int   g_esrc[N_EDGES];         // CSR column (src) array
__device__ __align__(16) half2 g_xh [(size_t)N_NODES * 32];  // x * oisq (128B rows)
__device__ __align__(16) half2 g_h1h[(size_t)N_NODES * 32];  // h1 * oisq
__device__ __align__(16) half  g_W1h[D * D];
__device__ __align__(16) half  g_W2h[D * D];

// ---------------- degree histogram (4 edges/thread) ----------------
// counters are zero on entry: BSS-zero on first call, re-zeroed by k_alloc.
__global__ void k_deg(const int* __restrict__ src, const int* __restrict__ dst) {
    int t = blockIdx.x * blockDim.x + threadIdx.x;
    int e0 = t * 4;
    if (e0 + 4 <= N_EDGES) {
        int4 s = *(const int4*)(src + e0);
        int4 d = *(const int4*)(dst + e0);
        atomicAdd(&g_degOi[s.x], 1); atomicAdd(&g_degOi[s.y], 1);
        atomicAdd(&g_degOi[s.z], 1); atomicAdd(&g_degOi[s.w], 1);
        atomicAdd(&g_degIi[d.x], 1); atomicAdd(&g_degIi[d.y], 1);
        atomicAdd(&g_degIi[d.z], 1); atomicAdd(&g_degIi[d.w], 1);
    } else {
        for (int e = e0; e < N_EDGES; e++) {
            atomicAdd(&g_degOi[src[e]], 1);
            atomicAdd(&g_degIi[dst[e]], 1);
        }
    }
}

// ---------------- row allocation + norms; zero counters for next replay ------
__global__ void k_alloc() {
    int i = blockIdx.x * blockDim.x + threadIdx.x;
    if (i >= N_NODES) return;
    int di = g_degIi[i];
    int dO = g_degOi[i];
    int row = atomicAdd(&g_total, di);     // grouping only; order irrelevant
    g_rows[i] = make_int2(row, di);
    g_cursor[i] = row;
    g_oisq[i] = rsqrtf((float)max(dO, 1));
    g_iisq[i] = rsqrtf((float)max(di, 1));
    g_degOi[i] = 0;                        // reset for next replay
    g_degIi[i] = 0;
}

// -------- convert x -> fp16 (pre-scaled by oisq); W1/W2 -> fp16; reset total --
__global__ void k_convert(const float* __restrict__ x,
                          const float* __restrict__ W1,
                          const float* __restrict__ W2) {
    int t = blockIdx.x * blockDim.x + threadIdx.x;
    if (t == 0) g_total = 0;
    if (t < D * D)          g_W1h[t] = __float2half(W1[t]);
    else if (t < 2 * D * D) g_W2h[t - D * D] = __float2half(W2[t - D * D]);
    if (t >= N_NODES * (D / 4)) return;
    int node = t >> 4;                     // 16 float4 per row
    float sc = g_oisq[node];
    float4 v = __ldg((const float4*)x + t);
    g_xh[t * 2 + 0] = __floats2half2_rn(v.x * sc, v.y * sc);
    g_xh[t * 2 + 1] = __floats2half2_rn(v.z * sc, v.w * sc);
}

// ---------------- CSR fill (4 edges/thread) ----------------
__global__ void k_fill(const int* __restrict__ src, const int* __restrict__ dst) {
    int t = blockIdx.x * blockDim.x + threadIdx.x;
    int e0 = t * 4;
    if (e0 + 4 <= N_EDGES) {
        int4 s = *(const int4*)(src + e0);
        int4 d = *(const int4*)(dst + e0);
        int p0 = atomicAdd(&g_cursor[d.x], 1);
        int p1 = atomicAdd(&g_cursor[d.y], 1);
        int p2 = atomicAdd(&g_cursor[d.z], 1);
        int p3 = atomicAdd(&g_cursor[d.w], 1);
        g_esrc[p0] = s.x; g_esrc[p1] = s.y;
        g_esrc[p2] = s.z; g_esrc[p3] = s.w;
    } else {
        for (int e = e0; e < N_EDGES; e++)
            g_esrc[atomicAdd(&g_cursor[dst[e]], 1)] = src[e];
    }
}

// =====================================================================
// Fused layers: fp16 gather (4 lanes/node, 8 nodes/warp, unroll x2)
//   -> half smem tile -> wmma 16x16x16 HMMA (fp32 acc) -> epilogue
// Block: 256 threads, 64 nodes.
// =====================================================================

#define ACC_U4(V, A)                                                \
    do {                                                            \
        const half2* hv = (const half2*)&(V);                       \
        float2 f0 = __half22float2(hv[0]);                          \
        float2 f1 = __half22float2(hv[1]);                          \
        float2 f2 = __half22float2(hv[2]);                          \
        float2 f3 = __half22float2(hv[3]);                          \
        (A)[0].x += f0.x; (A)[0].y += f0.y;                         \
        (A)[1].x += f1.x; (A)[1].y += f1.y;                         \
        (A)[2].x += f2.x; (A)[2].y += f2.y;                         \
        (A)[3].x += f3.x; (A)[3].y += f3.y;                         \
    } while (0)

// lane l of 4-lane group covers feats [8l,8l+8) and [32+8l,32+8l+8)
__device__ __forceinline__ void group_aggregate(const uint4* __restrict__ feat,
                                                int node, int l,
                                                float2 accA[4], float2 accB[4]) {
    int2 rd = g_rows[node];
    int start = rd.x, deg = rd.y;
    int i = 0;
    int s0 = 0, s1 = 0;
    if (deg >= 2) { s0 = __ldg(&g_esrc[start]); s1 = __ldg(&g_esrc[start + 1]); }
    for (; i + 2 <= deg; ) {
        int t0 = s0, t1 = s1;
        i += 2;
        if (i + 2 <= deg) {
            s0 = __ldg(&g_esrc[start + i]);
            s1 = __ldg(&g_esrc[start + i + 1]);
        }
        uint4 va0 = __ldg(feat + (size_t)t0 * 8 + l);
        uint4 vb0 = __ldg(feat + (size_t)t0 * 8 + 4 + l);
        uint4 va1 = __ldg(feat + (size_t)t1 * 8 + l);
        uint4 vb1 = __ldg(feat + (size_t)t1 * 8 + 4 + l);
        ACC_U4(va0, accA); ACC_U4(vb0, accB);
        ACC_U4(va1, accA); ACC_U4(vb1, accB);
    }
    if (i < deg) {
        int t0 = __ldg(&g_esrc[start + i]);
        uint4 va0 = __ldg(feat + (size_t)t0 * 8 + l);
        uint4 vb0 = __ldg(feat + (size_t)t0 * 8 + 4 + l);
        ACC_U4(va0, accA); ACC_U4(vb0, accB);
    }
}

// aggregate block's 64 nodes -> half tile sA[64][LDA] (scaled by iisq)
__device__ __forceinline__ void aggregate_phase(const uint4* __restrict__ feat,
                                                int base, int tid, half* sA) {
    int g = tid >> 2, l = tid & 3;
    int gn = base + g;
    float2 accA[4] = {{0,0},{0,0},{0,0},{0,0}};
    float2 accB[4] = {{0,0},{0,0},{0,0},{0,0}};
    if (gn < N_NODES) {
        group_aggregate(feat, gn, l, accA, accB);
        float fi = g_iisq[gn];
#pragma unroll
        for (int j = 0; j < 4; j++) {
            accA[j].x *= fi; accA[j].y *= fi;
            accB[j].x *= fi; accB[j].y *= fi;
        }
    }
    half2 hA[4], hB[4];
#pragma unroll
    for (int j = 0; j < 4; j++) {
        hA[j] = __floats2half2_rn(accA[j].x, accA[j].y);
        hB[j] = __floats2half2_rn(accB[j].x, accB[j].y);
    }
    *(uint4*)&sA[g * LDA + 8 * l]      = *(uint4*)hA;
    *(uint4*)&sA[g * LDA + 32 + 8 * l] = *(uint4*)hB;
}

// wmma GEMM: sC[64][LDC] = sA[64][LDA] (row) @ sB[64][LDA] (row, k x n)
__device__ __forceinline__ void wmma_gemm(const half* sA, const half* sB,
                                          float* sC, int tid) {
    int w = tid >> 5;                 // 8 warps
    int mi = w >> 1;                  // 4 m-tiles
    int ni0 = (w & 1) * 2;            // 2 n-tiles per warp
#pragma unroll
    for (int nt = 0; nt < 2; nt++) {
        int ni = ni0 + nt;
        wmma::fragment<wmma::accumulator, 16, 16, 16, float> c;
        wmma::fill_fragment(c, 0.f);
#pragma unroll
        for (int kk = 0; kk < 4; kk++) {
            wmma::fragment<wmma::matrix_a, 16, 16, 16, half, wmma::row_major> a;
            wmma::fragment<wmma::matrix_b, 16, 16, 16, half, wmma::row_major> bf;
            wmma::load_matrix_sync(a, sA + mi * 16 * LDA + kk * 16, LDA);
            wmma::load_matrix_sync(bf, sB + kk * 16 * LDA + ni * 16, LDA);
            wmma::mma_sync(c, a, bf, c);
        }
        wmma::store_matrix_sync(sC + mi * 16 * LDC + ni * 16, c, LDC,
                                wmma::mem_row_major);
    }
}

// Layer 1
__global__ void __launch_bounds__(256) k_layer1(const float* __restrict__ b) {
    __shared__ __align__(16) half  sA[64 * LDA];
    __shared__ __align__(16) half  sB[64 * LDA];
    __shared__ __align__(16) float sC[64 * LDC];
    __shared__ float sBias[D];
    int tid = threadIdx.x;
    int base = blockIdx.x * 64;

    for (int i = tid; i < D * D; i += 256)
        sB[(i >> 6) * LDA + (i & 63)] = g_W1h[i];
    if (tid < D) sBias[tid] = b[tid];

    aggregate_phase((const uint4*)g_xh, base, tid, sA);
    __syncthreads();

    wmma_gemm(sA, sB, sC, tid);
    __syncthreads();

    // epilogue: bias + lrelu + *oisq -> fp16 global
    int g = tid >> 2, q = tid & 3;
    int on = base + g;
    if (on < N_NODES) {
        float sc = __ldg(&g_oisq[on]);
        half2 hv[8];
#pragma unroll
        for (int j = 0; j < 8; j++) {
            int c0 = q * 16 + 2 * j;
            float y0 = sC[g * LDC + c0]     + sBias[c0];
            float y1 = sC[g * LDC + c0 + 1] + sBias[c0 + 1];
            y0 = (y0 > 0.f) ? y0 : NEG_SLOPE * y0;
            y1 = (y1 > 0.f) ? y1 : NEG_SLOPE * y1;
            hv[j] = __floats2half2_rn(y0 * sc, y1 * sc);
        }
        uint4* dst = (uint4*)&g_h1h[(size_t)on * 32];
        dst[q * 2 + 0] = ((uint4*)hv)[0];
        dst[q * 2 + 1] = ((uint4*)hv)[1];
    }
}

// Layer 2 + classifier
__global__ void __launch_bounds__(256) k_layer2(
    const float* __restrict__ b2,
    const float* __restrict__ Wc, const float* __restrict__ bc,
    float* __restrict__ out)
{
    __shared__ __align__(16) half  sA[64 * LDA];
    __shared__ __align__(16) half  sB[64 * LDA];
    __shared__ __align__(16) float sC[64 * LDC];
    __shared__ float sBias[D];
    __shared__ float sWc[D * 2];
    int tid = threadIdx.x;
    int base = blockIdx.x * 64;

    for (int i = tid; i < D * D; i += 256)
        sB[(i >> 6) * LDA + (i & 63)] = g_W2h[i];
    if (tid < D) sBias[tid] = b2[tid];
    if (tid >= 64 && tid < 64 + D * 2) sWc[tid - 64] = Wc[tid - 64];

    aggregate_phase((const uint4*)g_h1h, base, tid, sA);
    __syncthreads();

    wmma_gemm(sA, sB, sC, tid);
    __syncthreads();

    // epilogue: bias + lrelu, in-place in sC (same thread reads/writes)
    int g = tid >> 2, q = tid & 3;
#pragma unroll
    for (int j = 0; j < 16; j++) {
        int c0 = q * 16 + j;
        float y = sC[g * LDC + c0] + sBias[c0];
        y = (y > 0.f) ? y : NEG_SLOPE * y;
        sC[g * LDC + c0] = y;
    }
    __syncthreads();

    // classifier: out[n][c] = bc[c] + sum_k h2[n][k] * Wc[k][c]
    if (tid < 128) {
        int n = tid >> 1, c = tid & 1;
        int on = base + n;
        if (on < N_NODES) {
            float s = bc[c];
#pragma unroll
            for (int k = 0; k < D; k++) s += sC[n * LDC + k] * sWc[k * 2 + c];
            out[(size_t)on * 2 + c] = s;
        }
    }
}

// ---------------- launch ----------------
extern "C" void kernel_launch(void* const* d_in, const int* in_sizes, int n_in,
                              void* d_out, int out_size) {
    const float* x   = (const float*)d_in[0];
    const int*   src = (const int*)  d_in[1];
    const int*   dst = (const int*)  d_in[2];
    const float* W1  = (const float*)d_in[3];
    const float* b1  = (const float*)d_in[4];
    const float* W2  = (const float*)d_in[5];
    const float* b2  = (const float*)d_in[6];
    const float* Wc  = (const float*)d_in[7];
    const float* bc  = (const float*)d_in[8];
    float* out = (float*)d_out;

    const int edgeThreads = (N_EDGES + 3) / 4;
    k_deg    <<<(edgeThreads + 255) / 256, 256>>>(src, dst);
    k_alloc  <<<(N_NODES + 255) / 256, 256>>>();
    k_convert<<<(N_NODES * (D / 4) + 255) / 256, 256>>>(x, W1, W2);
    k_fill   <<<(edgeThreads + 255) / 256, 256>>>(src, dst);

    k_layer1<<<(N_NODES + 63) / 64, 256>>>(b1);
    k_layer2<<<(N_NODES + 63) / 64, 256>>>(b2, Wc, bc, out);
}